// round 11
// baseline (speedup 1.0000x reference)
#include <cuda_runtime.h>
#include <cuda_fp16.h>
#include <cstdint>
#include <cstddef>

#define BATCH   2
#define LSEQ    2048
#define BL      4096
#define DMODEL  1024
#define DHALF   512
#define DINNER  1024
#define DSTATE  128
#define NH      16
#define HD      64
#define CONVDIM 1280
#define DPROJ   2320

// ---------------- scratch ----------------
__device__ __half g_uh[2][BL][DHALF];
__device__ __half g_zxh[2][BL][DPROJ];
__device__ float  g_xc[2][BL][CONVDIM];
__device__ float  g_dt[2][BL][NH];
__device__ float  g_dA[2][BL][NH];
__device__ float  g_y[2][BL][DINNER];
__device__ __half g_yh[2][BL][DINNER];
__device__ __half g_odh[BL][DMODEL];
__device__ __half wh_in[2][DPROJ * DHALF];
__device__ __half wh_out[2][DHALF * DINNER];
__device__ __half wh_op[DMODEL * DMODEL];

// ---------------- helpers ----------------
__device__ __forceinline__ void cp16(uint32_t dst, const void* src, int szbytes) {
  asm volatile("cp.async.cg.shared.global [%0], [%1], 16, %2;"
               :: "r"(dst), "l"(src), "r"(szbytes) : "memory");
}
#define CP_COMMIT() asm volatile("cp.async.commit_group;" ::: "memory")
#define CP_WAIT1()  asm volatile("cp.async.wait_group 1;" ::: "memory")
#define CP_WAIT0()  asm volatile("cp.async.wait_group 0;" ::: "memory")

__device__ __forceinline__ void mma16816(float* c, const uint32_t* a, const uint32_t* b) {
  asm volatile(
    "mma.sync.aligned.m16n8k16.row.col.f32.f16.f16.f32 "
    "{%0,%1,%2,%3}, {%4,%5,%6,%7}, {%8,%9}, {%0,%1,%2,%3};"
    : "+f"(c[0]), "+f"(c[1]), "+f"(c[2]), "+f"(c[3])
    : "r"(a[0]), "r"(a[1]), "r"(a[2]), "r"(a[3]), "r"(b[0]), "r"(b[1]));
}
#define LDSM_X4(r0, r1, r2, r3, addr) \
  asm volatile("ldmatrix.sync.aligned.m8n8.x4.shared.b16 {%0,%1,%2,%3}, [%4];" \
               : "=r"(r0), "=r"(r1), "=r"(r2), "=r"(r3) : "r"(addr))

// ---------------- K1: fused weight-convert + RMSNorm/split/flip ----------------
__global__ __launch_bounds__(256) void k_pre(
    const float* __restrict__ x, const float* __restrict__ norm_w,
    const float* __restrict__ s0, __half* __restrict__ d0, int n0,
    const float* __restrict__ s1, __half* __restrict__ d1, int n1,
    const float* __restrict__ s2, __half* __restrict__ d2, int n2,
    const float* __restrict__ s3, __half* __restrict__ d3, int n3,
    const float* __restrict__ s4, __half* __restrict__ d4, int n4)
{
  int tid = threadIdx.x;
  if (blockIdx.y < 5) {
    const float* s; __half* d; int n;
    switch (blockIdx.y) {
      case 0: s = s0; d = d0; n = n0; break;
      case 1: s = s1; d = d1; n = n1; break;
      case 2: s = s2; d = d2; n = n2; break;
      case 3: s = s3; d = d3; n = n3; break;
      default: s = s4; d = d4; n = n4; break;
    }
    int i = (blockIdx.x * 256 + tid) * 4;
    if (i < n) {
      float4 v = *(const float4*)(s + i);
      *(__half2*)(d + i)     = __floats2half2_rn(v.x, v.y);
      *(__half2*)(d + i + 2) = __floats2half2_rn(v.z, v.w);
    }
    return;
  }
  int row = blockIdx.x;
  const float* xr = x + (size_t)row * DMODEL;
  float v[4]; float ss = 0.f;
#pragma unroll
  for (int i = 0; i < 4; i++) { v[i] = xr[tid + i * 256]; ss += v[i] * v[i]; }
  __shared__ float red[256];
  red[tid] = ss; __syncthreads();
  for (int s = 128; s > 0; s >>= 1) { if (tid < s) red[tid] += red[tid + s]; __syncthreads(); }
  float scale = rsqrtf(red[0] * (1.f / DMODEL) + 1e-5f);
  int l = row & 2047, rrow = (row & ~2047) + (2047 - l);
#pragma unroll
  for (int i = 0; i < 4; i++) {
    int c = tid + i * 256;
    float val = v[i] * scale * norm_w[c];
    if (c < DHALF) g_uh[0][row][c] = __float2half(val);
    else           g_uh[1][rrow][c - DHALF] = __float2half(val);
  }
}

// ---------------- K2: fp16 GEMM, 2-stage, warp 64x64, TKS=64, z merges dirs ----------------
#define TKS    64
#define SROW   72
#define TILEH  (128 * SROW)
#define STAGEB (2 * TILEH * 2)
#define GSMEM  (2 * STAGEB)

__global__ __launch_bounds__(128)
void k_gemm_h(const __half* __restrict__ A, const __half* __restrict__ W,
              const float* __restrict__ bias, const float* __restrict__ res,
              float* __restrict__ Cf, __half* __restrict__ Ch,
              int Nw, int K, int ldc, int col_off, int colOffZ, int flipZ,
              size_t aStrideZ, size_t wStrideZ, size_t cStrideZ)
{
  extern __shared__ __half sm[];
  int z = blockIdx.z;
  A += (size_t)z * aStrideZ;
  W += (size_t)z * wStrideZ;
  if (Cf) Cf += (size_t)z * cStrideZ; else Ch += (size_t)z * cStrideZ;
  int coff = col_off + z * colOffZ;
  int flip = flipZ ? z : 0;

  int tid = threadIdx.x;
  int wid = tid >> 5, lane = tid & 31;
  int g = lane >> 2, tg = lane & 3;
  int wm = wid & 1, wn = wid >> 1;
  int row0 = blockIdx.y * 128, col0 = blockIdx.x * 128;

  uint32_t sbase = (uint32_t)__cvta_generic_to_shared(sm);

  int arow = lane & 15, acol = (lane >> 4) * 8;
  int brow = ((lane >> 4) & 1) * 8 + (lane & 7);
  int bcol = ((lane >> 3) & 1) * 8;

  float acc[4][8][4];
#pragma unroll
  for (int mi = 0; mi < 4; mi++)
#pragma unroll
    for (int ni = 0; ni < 8; ni++)
#pragma unroll
      for (int r = 0; r < 4; r++) acc[mi][ni][r] = 0.f;

  int KT = K / TKS;

#define LOAD_STAGE(stg, k0)                                                       \
  {                                                                               \
    uint32_t ab = sbase + (stg) * STAGEB;                                         \
    uint32_t bb = ab + TILEH * 2;                                                 \
    _Pragma("unroll")                                                             \
    for (int i = 0; i < 8; i++) {                                                 \
      int idx = tid + i * 128;                                                    \
      int r = idx >> 3, q = idx & 7;                                              \
      cp16(ab + (uint32_t)((r * SROW + q * 8) * 2),                               \
           A + (size_t)(row0 + r) * K + (k0) + q * 8, 16);                        \
      int wr = col0 + r;                                                          \
      const __half* ws = W + (size_t)(wr < Nw ? wr : 0) * K + (k0) + q * 8;       \
      cp16(bb + (uint32_t)((r * SROW + q * 8) * 2), ws, (wr < Nw) ? 16 : 0);      \
    }                                                                             \
    CP_COMMIT();                                                                  \
  }

  LOAD_STAGE(0, 0)

  for (int kt = 0; kt < KT; kt++) {
    int buf = kt & 1;
    if (kt + 1 < KT) {
      LOAD_STAGE(buf ^ 1, (kt + 1) * TKS)
      CP_WAIT1();
    } else {
      CP_WAIT0();
    }
    __syncthreads();

    uint32_t ab = sbase + (uint32_t)buf * STAGEB;
    uint32_t bb = ab + TILEH * 2;
#pragma unroll
    for (int kk = 0; kk < TKS; kk += 16) {
      uint32_t af[4][4], bf[8][2];
#pragma unroll
      for (int mi = 0; mi < 4; mi++) {
        uint32_t addr = ab + (uint32_t)(((wm * 64 + mi * 16 + arow) * SROW + kk + acol) * 2);
        LDSM_X4(af[mi][0], af[mi][1], af[mi][2], af[mi][3], addr);
      }
#pragma unroll
      for (int nb = 0; nb < 4; nb++) {
        uint32_t addr = bb + (uint32_t)(((wn * 64 + nb * 16 + brow) * SROW + kk + bcol) * 2);
        LDSM_X4(bf[nb * 2][0], bf[nb * 2][1], bf[nb * 2 + 1][0], bf[nb * 2 + 1][1], addr);
      }
#pragma unroll
      for (int mi = 0; mi < 4; mi++)
#pragma unroll
        for (int ni = 0; ni < 8; ni++)
          mma16816(acc[mi][ni], af[mi], bf[ni]);
    }
    __syncthreads();
  }

#pragma unroll
  for (int mi = 0; mi < 4; mi++) {
#pragma unroll
    for (int hf = 0; hf < 2; hf++) {
      int m = row0 + wm * 64 + mi * 16 + g + hf * 8;
      int orow = flip ? ((m & ~2047) + (2047 - (m & 2047))) : m;
      const float* rrow = res ? (res + (size_t)m * ldc + coff) : nullptr;
#pragma unroll
      for (int ni = 0; ni < 8; ni++) {
        int n = col0 + wn * 64 + ni * 8 + 2 * tg;
        if (n < Nw) {
          float v0 = acc[mi][ni][hf * 2 + 0];
          float v1 = acc[mi][ni][hf * 2 + 1];
          if (bias) { v0 += bias[n]; v1 += bias[n + 1]; }
          if (rrow) { v0 += rrow[n]; v1 += rrow[n + 1]; }
          if (Cf) {
            float* crow = Cf + (size_t)orow * ldc + coff;
            crow[n] = v0; crow[n + 1] = v1;
          } else {
            __half* crow = Ch + (size_t)orow * ldc + coff;
            crow[n] = __float2half(v0); crow[n + 1] = __float2half(v1);
          }
        }
      }
    }
  }
}

// ---------------- K3: conv(4)+SiLU via smem staging, softplus(dt), dA ----------------
__global__ __launch_bounds__(256) void k_conv(
    const float* __restrict__ cw0, const float* __restrict__ cb0,
    const float* __restrict__ db0, const float* __restrict__ al0,
    const float* __restrict__ cw1, const float* __restrict__ cb1,
    const float* __restrict__ db1, const float* __restrict__ al1)
{
  int dir = blockIdx.x >> 12;
  int row = blockIdx.x & 4095;
  int tid = threadIdx.x;
  const float* conv_w  = dir ? cw1 : cw0;
  const float* conv_b  = dir ? cb1 : cb0;
  const float* dt_bias = dir ? db1 : db0;
  const float* A_log   = dir ? al1 : al0;
  int l = row & 2047, rb = row & ~2047;

  __shared__ __half sxb[4][CONVDIM];
  const int VPR = CONVDIM / 8;
  for (int i = tid; i < 4 * VPR; i += 256) {
    int kr = i / VPR, off = (i - kr * VPR) * 8;
    int ls = l - 3 + kr;
    if (ls >= 0)
      *(uint4*)&sxb[kr][off] = *(const uint4*)&g_zxh[dir][rb + ls][DINNER + off];
  }
  __syncthreads();

  for (int c = tid; c < CONVDIM; c += 256) {
    float acc = conv_b[c];
#pragma unroll
    for (int k = 0; k < 4; k++) {
      int ls = l - 3 + k;
      if (ls >= 0) acc = fmaf(conv_w[c * 4 + k], __half2float(sxb[k][c]), acc);
    }
    g_xc[dir][row][c] = acc / (1.f + expf(-acc));
  }
  if (tid < NH) {
    float d = __half2float(g_zxh[dir][row][DINNER + CONVDIM + tid]) + dt_bias[tid];
    float sp = (d > 20.f) ? d : log1pf(expf(d));
    g_dt[dir][row][tid] = sp;
    g_dA[dir][row][tid] = expf(-sp * expf(A_log[tid]));
  }
}

// ---------------- K4: scan — 256 blocks x 128 thr, 1p/thread, cp.async double-buffer ----------------
#define TT 32
#define NCK (LSEQ / TT)
// dynamic smem layout (floats):
//  B:  [2][TT][128]  @ 0        (8192)
//  C:  [2][TT][128]  @ 8192     (8192)
//  X:  [2][TT][16]   @ 16384    (1024)
//  DT: [2][TT]       @ 17408    (64)
//  DA: [2][TT]       @ 17472    (64)
#define SC_SMEM (17536 * 4)

__global__ __launch_bounds__(128) void k_scan(const float* __restrict__ Df,
                                              const float* __restrict__ Db)
{
  extern __shared__ float sms[];
  int blk = blockIdx.x;               // 256 = dir(2) x b(2) x hh(16) x pq(4)
  int dir = blk >> 7;
  int rem = blk & 127;
  int b  = rem >> 6;
  int hh = (rem >> 2) & 15;
  int pq = rem & 3;
  int tid = threadIdx.x;
  int pl = tid >> 3, g = tid & 7;     // pl 0..15, g 0..7; thread owns p=pl, n=g+8j
  int rowbase = b << 11;
  int xcol = hh * HD + pq * 16;
  uint32_t sb = (uint32_t)__cvta_generic_to_shared(sms);

  float h[16];
#pragma unroll
  for (int j = 0; j < 16; j++) h[j] = 0.f;
  float Dh = dir ? Db[hh] : Df[hh];

#define SCAN_LOAD(buf, t0)                                                          \
  {                                                                                 \
    _Pragma("unroll")                                                               \
    for (int it = 0; it < 8; it++) {                                                \
      int idx = tid + it * 128;                                                     \
      int tt = idx >> 5, q4 = (idx & 31) * 4;                                       \
      const float* srow = &g_xc[dir][rowbase + (t0) + tt][DINNER];                  \
      cp16(sb + (uint32_t)((((buf) * TT + tt) * 128 + q4) * 4), srow + q4, 16);     \
      cp16(sb + (uint32_t)((8192 + ((buf) * TT + tt) * 128 + q4) * 4),              \
           srow + DSTATE + q4, 16);                                                 \
    }                                                                               \
    { int tt = tid >> 2, q4 = (tid & 3) * 4;                                        \
      cp16(sb + (uint32_t)((16384 + ((buf) * TT + tt) * 16 + q4) * 4),              \
           &g_xc[dir][rowbase + (t0) + tt][xcol + q4], 16); }                       \
    if (tid < TT) {                                                                 \
      sms[17408 + (buf) * TT + tid] = g_dt[dir][rowbase + (t0) + tid][hh];          \
      sms[17472 + (buf) * TT + tid] = g_dA[dir][rowbase + (t0) + tid][hh];          \
    }                                                                               \
    CP_COMMIT();                                                                    \
  }

  SCAN_LOAD(0, 0)

  int buf = 0;
  for (int c = 0; c < NCK; c++) {
    if (c + 1 < NCK) {
      SCAN_LOAD(buf ^ 1, (c + 1) * TT)
      CP_WAIT1();
    } else {
      CP_WAIT0();
    }
    __syncthreads();

    const float* Bc = &sms[buf * TT * 128];
    const float* Cc = &sms[8192 + buf * TT * 128];
    const float* Xc = &sms[16384 + buf * TT * 16];
    const float* DTc = &sms[17408 + buf * TT];
    const float* DAc = &sms[17472 + buf * TT];
#pragma unroll 2
    for (int tt = 0; tt < TT; tt++) {
      float dA = DAc[tt];
      float s  = DTc[tt] * Xc[tt * 16 + pl];
      float a0 = 0.f, a1 = 0.f, a2 = 0.f, a3 = 0.f;
#pragma unroll
      for (int j4 = 0; j4 < 4; j4++) {
#pragma unroll
        for (int jj = 0; jj < 4; jj++) {
          int j = j4 * 4 + jj;
          int n = g + (j << 3);
          float bv = Bc[tt * 128 + n];
          float cv = Cc[tt * 128 + n];
          h[j] = fmaf(dA, h[j], s * bv);
          if (jj == 0) a0 = fmaf(h[j], cv, a0);
          else if (jj == 1) a1 = fmaf(h[j], cv, a1);
          else if (jj == 2) a2 = fmaf(h[j], cv, a2);
          else a3 = fmaf(h[j], cv, a3);
        }
      }
      float acc = (a0 + a1) + (a2 + a3);
      acc += __shfl_xor_sync(0xffffffffu, acc, 1);
      acc += __shfl_xor_sync(0xffffffffu, acc, 2);
      acc += __shfl_xor_sync(0xffffffffu, acc, 4);
      if (g == 0)
        g_y[dir][rowbase + c * TT + tt][xcol + pl] = acc + Dh * Xc[tt * 16 + pl];
    }
    __syncthreads();
    buf ^= 1;
  }
}

// ---------------- K5: gating + gated RMSNorm -> fp16, both dirs ----------------
__global__ __launch_bounds__(256) void k_gate(const float* __restrict__ gw0,
                                              const float* __restrict__ gw1)
{
  int dir = blockIdx.x >> 12;
  int row = blockIdx.x & 4095;
  int tid = threadIdx.x;
  const float* gnorm_w = dir ? gw1 : gw0;
  float vals[4]; float ss = 0.f;
#pragma unroll
  for (int i = 0; i < 4; i++) {
    int c = tid + i * 256;
    float yv = g_y[dir][row][c];
    float z = __half2float(g_zxh[dir][row][c]);
    float gv = yv * (z / (1.f + expf(-z)));
    vals[i] = gv; ss += gv * gv;
  }
  __shared__ float red[256];
  red[tid] = ss; __syncthreads();
  for (int s = 128; s > 0; s >>= 1) { if (tid < s) red[tid] += red[tid + s]; __syncthreads(); }
  float sc = rsqrtf(red[0] * (1.f / DINNER) + 1e-5f);
#pragma unroll
  for (int i = 0; i < 4; i++) {
    int c = tid + i * 256;
    g_yh[dir][row][c] = __float2half(vals[i] * sc * gnorm_w[c]);
  }
}

// ---------------- launch ----------------
extern "C" void kernel_launch(void* const* d_in, const int* in_sizes, int n_in,
                              void* d_out, int out_size)
{
  (void)in_sizes; (void)n_in; (void)out_size;
  const float* x      = (const float*)d_in[0];
  const float* norm_w = (const float*)d_in[1];
  const float* op_w   = (const float*)d_in[2];
  const float* op_b   = (const float*)d_in[3];
  const float* in_w[2]    = {(const float*)d_in[4],  (const float*)d_in[12]};
  const float* conv_w[2]  = {(const float*)d_in[5],  (const float*)d_in[13]};
  const float* conv_b[2]  = {(const float*)d_in[6],  (const float*)d_in[14]};
  const float* dt_bias[2] = {(const float*)d_in[7],  (const float*)d_in[15]};
  const float* A_log[2]   = {(const float*)d_in[8],  (const float*)d_in[16]};
  const float* Dvec[2]    = {(const float*)d_in[9],  (const float*)d_in[17]};
  const float* gnorm[2]   = {(const float*)d_in[10], (const float*)d_in[18]};
  const float* outp_w[2]  = {(const float*)d_in[11], (const float*)d_in[19]};
  float* out = (float*)d_out;

  __half *pwi, *pwo, *pwp, *puh, *pyh, *podh, *pzxh;
  cudaGetSymbolAddress((void**)&pwi, wh_in);
  cudaGetSymbolAddress((void**)&pwo, wh_out);
  cudaGetSymbolAddress((void**)&pwp, wh_op);
  cudaGetSymbolAddress((void**)&puh, g_uh);
  cudaGetSymbolAddress((void**)&pyh, g_yh);
  cudaGetSymbolAddress((void**)&podh, g_odh);
  cudaGetSymbolAddress((void**)&pzxh, g_zxh);

  static int attr_set = 0;
  if (!attr_set) {
    cudaFuncSetAttribute(k_gemm_h, cudaFuncAttributeMaxDynamicSharedMemorySize, GSMEM);
    cudaFuncSetAttribute(k_scan, cudaFuncAttributeMaxDynamicSharedMemorySize, SC_SMEM);
    attr_set = 1;
  }

  // 1: weight convert + rmsnorm (fused)
  k_pre<<<dim3(BL, 6), 256>>>(
      x, norm_w,
      in_w[0],   pwi,                  DPROJ * DHALF,
      in_w[1],   pwi + DPROJ * DHALF,  DPROJ * DHALF,
      outp_w[0], pwo,                  DHALF * DINNER,
      outp_w[1], pwo + DHALF * DINNER, DHALF * DINNER,
      op_w,      pwp,                  DMODEL * DMODEL);

  // 2: in-proj, both dirs, fp16 output
  k_gemm_h<<<dim3((DPROJ + 127) / 128, BL / 128, 2), 128, GSMEM>>>(
      puh, pwi, nullptr, nullptr, nullptr, pzxh,
      DPROJ, DHALF, DPROJ, 0, 0, 0,
      (size_t)BL * DHALF, (size_t)DPROJ * DHALF, (size_t)BL * DPROJ);

  // 3: conv
  k_conv<<<2 * BL, 256>>>(conv_w[0], conv_b[0], dt_bias[0], A_log[0],
                          conv_w[1], conv_b[1], dt_bias[1], A_log[1]);

  // 4: scan (256 blocks, dynamic smem)
  k_scan<<<256, 128, SC_SMEM>>>(Dvec[0], Dvec[1]);

  // 5: gate
  k_gate<<<2 * BL, 256>>>(gnorm[0], gnorm[1]);

  // 6: out-proj, both dirs
  k_gemm_h<<<dim3(DHALF / 128, BL / 128, 2), 128, GSMEM>>>(
      pyh, pwo, nullptr, nullptr, nullptr, podh,
      DHALF, DINNER, DMODEL, 0, DHALF, 1,
      (size_t)BL * DINNER, (size_t)DHALF * DINNER, 0);

  // 7: final projection (+bias, +residual x)
  k_gemm_h<<<dim3(DMODEL / 128, BL / 128, 1), 128, GSMEM>>>(
      podh, pwp, op_b, x, out, nullptr,
      DMODEL, DMODEL, DMODEL, 0, 0, 0, 0, 0, 0);
}

// round 12
// speedup vs baseline: 1.2322x; 1.2322x over previous
#include <cuda_runtime.h>
#include <cuda_fp16.h>
#include <cstdint>
#include <cstddef>

#define BATCH   2
#define LSEQ    2048
#define BL      4096
#define DMODEL  1024
#define DHALF   512
#define DINNER  1024
#define DSTATE  128
#define NH      16
#define HD      64
#define CONVDIM 1280
#define DPROJ   2320

// ---------------- scratch ----------------
__device__ __half g_uh[2][BL][DHALF];
__device__ __half g_zxh[2][BL][DPROJ];
__device__ float  g_xc[2][BL][CONVDIM];
__device__ float  g_dt[2][BL][NH];
__device__ float  g_dA[2][BL][NH];
__device__ float  g_y[2][BL][DINNER];
__device__ __half g_yh[2][BL][DINNER];
__device__ __half g_odh[BL][DMODEL];
__device__ __half wh_in[2][DPROJ * DHALF];
__device__ __half wh_out[2][DHALF * DINNER];
__device__ __half wh_op[DMODEL * DMODEL];

// ---------------- helpers ----------------
__device__ __forceinline__ void cp16(uint32_t dst, const void* src, int szbytes) {
  asm volatile("cp.async.cg.shared.global [%0], [%1], 16, %2;"
               :: "r"(dst), "l"(src), "r"(szbytes) : "memory");
}
#define CP_COMMIT() asm volatile("cp.async.commit_group;" ::: "memory")
#define CP_WAIT1()  asm volatile("cp.async.wait_group 1;" ::: "memory")
#define CP_WAIT0()  asm volatile("cp.async.wait_group 0;" ::: "memory")

__device__ __forceinline__ void mma16816(float* c, const uint32_t* a, const uint32_t* b) {
  asm volatile(
    "mma.sync.aligned.m16n8k16.row.col.f32.f16.f16.f32 "
    "{%0,%1,%2,%3}, {%4,%5,%6,%7}, {%8,%9}, {%0,%1,%2,%3};"
    : "+f"(c[0]), "+f"(c[1]), "+f"(c[2]), "+f"(c[3])
    : "r"(a[0]), "r"(a[1]), "r"(a[2]), "r"(a[3]), "r"(b[0]), "r"(b[1]));
}
#define LDSM_X4(r0, r1, r2, r3, addr) \
  asm volatile("ldmatrix.sync.aligned.m8n8.x4.shared.b16 {%0,%1,%2,%3}, [%4];" \
               : "=r"(r0), "=r"(r1), "=r"(r2), "=r"(r3) : "r"(addr))

// ---------------- K1: fused weight-convert + RMSNorm/split/flip ----------------
__global__ __launch_bounds__(256) void k_pre(
    const float* __restrict__ x, const float* __restrict__ norm_w,
    const float* __restrict__ s0, __half* __restrict__ d0, int n0,
    const float* __restrict__ s1, __half* __restrict__ d1, int n1,
    const float* __restrict__ s2, __half* __restrict__ d2, int n2,
    const float* __restrict__ s3, __half* __restrict__ d3, int n3,
    const float* __restrict__ s4, __half* __restrict__ d4, int n4)
{
  int tid = threadIdx.x;
  if (blockIdx.y < 5) {
    const float* s; __half* d; int n;
    switch (blockIdx.y) {
      case 0: s = s0; d = d0; n = n0; break;
      case 1: s = s1; d = d1; n = n1; break;
      case 2: s = s2; d = d2; n = n2; break;
      case 3: s = s3; d = d3; n = n3; break;
      default: s = s4; d = d4; n = n4; break;
    }
    int i = (blockIdx.x * 256 + tid) * 4;
    if (i < n) {
      float4 v = *(const float4*)(s + i);
      *(__half2*)(d + i)     = __floats2half2_rn(v.x, v.y);
      *(__half2*)(d + i + 2) = __floats2half2_rn(v.z, v.w);
    }
    return;
  }
  int row = blockIdx.x;
  const float* xr = x + (size_t)row * DMODEL;
  float v[4]; float ss = 0.f;
#pragma unroll
  for (int i = 0; i < 4; i++) { v[i] = xr[tid + i * 256]; ss += v[i] * v[i]; }
  __shared__ float red[256];
  red[tid] = ss; __syncthreads();
  for (int s = 128; s > 0; s >>= 1) { if (tid < s) red[tid] += red[tid + s]; __syncthreads(); }
  float scale = rsqrtf(red[0] * (1.f / DMODEL) + 1e-5f);
  int l = row & 2047, rrow = (row & ~2047) + (2047 - l);
#pragma unroll
  for (int i = 0; i < 4; i++) {
    int c = tid + i * 256;
    float val = v[i] * scale * norm_w[c];
    if (c < DHALF) g_uh[0][row][c] = __float2half(val);
    else           g_uh[1][rrow][c - DHALF] = __float2half(val);
  }
}

// ---------------- K2: fp16 GEMM, 2-stage, warp 64x64, TKS=64, z merges dirs ----------------
#define TKS    64
#define SROW   72
#define TILEH  (128 * SROW)
#define STAGEB (2 * TILEH * 2)
#define GSMEM  (2 * STAGEB)

__global__ __launch_bounds__(128)
void k_gemm_h(const __half* __restrict__ A, const __half* __restrict__ W,
              const float* __restrict__ bias, const float* __restrict__ res,
              float* __restrict__ Cf, __half* __restrict__ Ch,
              int Nw, int K, int ldc, int col_off, int colOffZ, int flipZ,
              size_t aStrideZ, size_t wStrideZ, size_t cStrideZ)
{
  extern __shared__ __half sm[];
  int z = blockIdx.z;
  A += (size_t)z * aStrideZ;
  W += (size_t)z * wStrideZ;
  if (Cf) Cf += (size_t)z * cStrideZ; else Ch += (size_t)z * cStrideZ;
  int coff = col_off + z * colOffZ;
  int flip = flipZ ? z : 0;

  int tid = threadIdx.x;
  int wid = tid >> 5, lane = tid & 31;
  int g = lane >> 2, tg = lane & 3;
  int wm = wid & 1, wn = wid >> 1;
  int row0 = blockIdx.y * 128, col0 = blockIdx.x * 128;

  uint32_t sbase = (uint32_t)__cvta_generic_to_shared(sm);

  int arow = lane & 15, acol = (lane >> 4) * 8;
  int brow = ((lane >> 4) & 1) * 8 + (lane & 7);
  int bcol = ((lane >> 3) & 1) * 8;

  float acc[4][8][4];
#pragma unroll
  for (int mi = 0; mi < 4; mi++)
#pragma unroll
    for (int ni = 0; ni < 8; ni++)
#pragma unroll
      for (int r = 0; r < 4; r++) acc[mi][ni][r] = 0.f;

  int KT = K / TKS;

#define LOAD_STAGE(stg, k0)                                                       \
  {                                                                               \
    uint32_t ab = sbase + (stg) * STAGEB;                                         \
    uint32_t bb = ab + TILEH * 2;                                                 \
    _Pragma("unroll")                                                             \
    for (int i = 0; i < 8; i++) {                                                 \
      int idx = tid + i * 128;                                                    \
      int r = idx >> 3, q = idx & 7;                                              \
      cp16(ab + (uint32_t)((r * SROW + q * 8) * 2),                               \
           A + (size_t)(row0 + r) * K + (k0) + q * 8, 16);                        \
      int wr = col0 + r;                                                          \
      const __half* ws = W + (size_t)(wr < Nw ? wr : 0) * K + (k0) + q * 8;       \
      cp16(bb + (uint32_t)((r * SROW + q * 8) * 2), ws, (wr < Nw) ? 16 : 0);      \
    }                                                                             \
    CP_COMMIT();                                                                  \
  }

  LOAD_STAGE(0, 0)

  for (int kt = 0; kt < KT; kt++) {
    int buf = kt & 1;
    if (kt + 1 < KT) {
      LOAD_STAGE(buf ^ 1, (kt + 1) * TKS)
      CP_WAIT1();
    } else {
      CP_WAIT0();
    }
    __syncthreads();

    uint32_t ab = sbase + (uint32_t)buf * STAGEB;
    uint32_t bb = ab + TILEH * 2;
#pragma unroll
    for (int kk = 0; kk < TKS; kk += 16) {
      uint32_t af[4][4], bf[8][2];
#pragma unroll
      for (int mi = 0; mi < 4; mi++) {
        uint32_t addr = ab + (uint32_t)(((wm * 64 + mi * 16 + arow) * SROW + kk + acol) * 2);
        LDSM_X4(af[mi][0], af[mi][1], af[mi][2], af[mi][3], addr);
      }
#pragma unroll
      for (int nb = 0; nb < 4; nb++) {
        uint32_t addr = bb + (uint32_t)(((wn * 64 + nb * 16 + brow) * SROW + kk + bcol) * 2);
        LDSM_X4(bf[nb * 2][0], bf[nb * 2][1], bf[nb * 2 + 1][0], bf[nb * 2 + 1][1], addr);
      }
#pragma unroll
      for (int mi = 0; mi < 4; mi++)
#pragma unroll
        for (int ni = 0; ni < 8; ni++)
          mma16816(acc[mi][ni], af[mi], bf[ni]);
    }
    __syncthreads();
  }

#pragma unroll
  for (int mi = 0; mi < 4; mi++) {
#pragma unroll
    for (int hf = 0; hf < 2; hf++) {
      int m = row0 + wm * 64 + mi * 16 + g + hf * 8;
      int orow = flip ? ((m & ~2047) + (2047 - (m & 2047))) : m;
      const float* rrow = res ? (res + (size_t)m * ldc + coff) : nullptr;
#pragma unroll
      for (int ni = 0; ni < 8; ni++) {
        int n = col0 + wn * 64 + ni * 8 + 2 * tg;
        if (n < Nw) {
          float v0 = acc[mi][ni][hf * 2 + 0];
          float v1 = acc[mi][ni][hf * 2 + 1];
          if (bias) { v0 += bias[n]; v1 += bias[n + 1]; }
          if (rrow) { v0 += rrow[n]; v1 += rrow[n + 1]; }
          if (Cf) {
            float* crow = Cf + (size_t)orow * ldc + coff;
            crow[n] = v0; crow[n + 1] = v1;
          } else {
            __half* crow = Ch + (size_t)orow * ldc + coff;
            crow[n] = __float2half(v0); crow[n + 1] = __float2half(v1);
          }
        }
      }
    }
  }
}

// ---------------- K3: conv(4)+SiLU via smem staging, softplus(dt), dA ----------------
__global__ __launch_bounds__(256) void k_conv(
    const float* __restrict__ cw0, const float* __restrict__ cb0,
    const float* __restrict__ db0, const float* __restrict__ al0,
    const float* __restrict__ cw1, const float* __restrict__ cb1,
    const float* __restrict__ db1, const float* __restrict__ al1)
{
  int dir = blockIdx.x >> 12;
  int row = blockIdx.x & 4095;
  int tid = threadIdx.x;
  const float* conv_w  = dir ? cw1 : cw0;
  const float* conv_b  = dir ? cb1 : cb0;
  const float* dt_bias = dir ? db1 : db0;
  const float* A_log   = dir ? al1 : al0;
  int l = row & 2047, rb = row & ~2047;

  __shared__ __half sxb[4][CONVDIM];
  const int VPR = CONVDIM / 8;
  for (int i = tid; i < 4 * VPR; i += 256) {
    int kr = i / VPR, off = (i - kr * VPR) * 8;
    int ls = l - 3 + kr;
    if (ls >= 0)
      *(uint4*)&sxb[kr][off] = *(const uint4*)&g_zxh[dir][rb + ls][DINNER + off];
  }
  __syncthreads();

  for (int c = tid; c < CONVDIM; c += 256) {
    float acc = conv_b[c];
#pragma unroll
    for (int k = 0; k < 4; k++) {
      int ls = l - 3 + k;
      if (ls >= 0) acc = fmaf(conv_w[c * 4 + k], __half2float(sxb[k][c]), acc);
    }
    g_xc[dir][row][c] = acc / (1.f + expf(-acc));
  }
  if (tid < NH) {
    float d = __half2float(g_zxh[dir][row][DINNER + CONVDIM + tid]) + dt_bias[tid];
    float sp = (d > 20.f) ? d : log1pf(expf(d));
    g_dt[dir][row][tid] = sp;
    g_dA[dir][row][tid] = expf(-sp * expf(A_log[tid]));
  }
}

// ---------------- K4: scan — 256 blocks x 128 thr, 1p/thread, simple loads ----------------
#define TT 32
__global__ __launch_bounds__(128) void k_scan(const float* __restrict__ Df,
                                              const float* __restrict__ Db)
{
  int blk = blockIdx.x;               // 256 = dir(2) x b(2) x hh(16) x pq(4)
  int dir = blk >> 7;
  int rem = blk & 127;
  int b  = rem >> 6;
  int hh = (rem >> 2) & 15;
  int pq = rem & 3;
  int tid = threadIdx.x;
  int pl = tid >> 3, g = tid & 7;     // pl 0..15, g 0..7; thread owns p=pl, n=g+8j
  __shared__ float sB[TT][DSTATE];
  __shared__ float sC[TT][DSTATE];
  __shared__ float sx[TT][16];        // x for this block's 16 p-lanes
  __shared__ float ss[TT][16];        // dt * x (precomputed by loader)
  __shared__ float sdA[TT];
  float h[16];
#pragma unroll
  for (int j = 0; j < 16; j++) h[j] = 0.f;
  float Dh = dir ? Db[hh] : Df[hh];
  int rowbase = b << 11;
  int xcol = hh * HD + pq * 16;

  for (int t0 = 0; t0 < LSEQ; t0 += TT) {
    __syncthreads();
    // B/C: 32 rows x 128 floats, float4, 2048 items / 128 thr = 16 iters
    for (int i = tid; i < TT * DSTATE / 4; i += 128) {
      int tt = i >> 5, c4 = i & 31;
      int row = rowbase + t0 + tt;
      *(float4*)&sB[tt][c4 * 4] = *(const float4*)&g_xc[dir][row][DINNER + c4 * 4];
      *(float4*)&sC[tt][c4 * 4] = *(const float4*)&g_xc[dir][row][DINNER + DSTATE + c4 * 4];
    }
    // x and dt*x: 32 rows x 16, float4 x-loads
    for (int i = tid; i < TT * 4; i += 128) {
      int tt = i >> 2, q4 = (i & 3) * 4;
      int row = rowbase + t0 + tt;
      float4 xv = *(const float4*)&g_xc[dir][row][xcol + q4];
      float dtv = g_dt[dir][row][hh];
      *(float4*)&sx[tt][q4] = xv;
      ss[tt][q4 + 0] = dtv * xv.x;
      ss[tt][q4 + 1] = dtv * xv.y;
      ss[tt][q4 + 2] = dtv * xv.z;
      ss[tt][q4 + 3] = dtv * xv.w;
    }
    if (tid < TT) sdA[tid] = g_dA[dir][rowbase + t0 + tid][hh];
    __syncthreads();
#pragma unroll 4
    for (int tt = 0; tt < TT; tt++) {
      float dA = sdA[tt];
      float s  = ss[tt][pl];
      float a0 = 0.f, a1 = 0.f, a2 = 0.f, a3 = 0.f;
#pragma unroll
      for (int jj = 0; jj < 4; jj++) {
#pragma unroll
        for (int j4 = 0; j4 < 4; j4++) {
          int j = j4 * 4 + jj;
          int n = g + (j << 3);
          float bv = sB[tt][n];
          float cv = sC[tt][n];
          h[j] = fmaf(dA, h[j], s * bv);
          if (j4 == 0) a0 = fmaf(h[j], cv, a0);
          else if (j4 == 1) a1 = fmaf(h[j], cv, a1);
          else if (j4 == 2) a2 = fmaf(h[j], cv, a2);
          else a3 = fmaf(h[j], cv, a3);
        }
      }
      float acc = (a0 + a1) + (a2 + a3);
      acc += __shfl_xor_sync(0xffffffffu, acc, 1);
      acc += __shfl_xor_sync(0xffffffffu, acc, 2);
      acc += __shfl_xor_sync(0xffffffffu, acc, 4);
      if (g == 0)
        g_y[dir][rowbase + t0 + tt][xcol + pl] = acc + Dh * sx[tt][pl];
    }
  }
}

// ---------------- K5: gating + gated RMSNorm -> fp16, both dirs ----------------
__global__ __launch_bounds__(256) void k_gate(const float* __restrict__ gw0,
                                              const float* __restrict__ gw1)
{
  int dir = blockIdx.x >> 12;
  int row = blockIdx.x & 4095;
  int tid = threadIdx.x;
  const float* gnorm_w = dir ? gw1 : gw0;
  float vals[4]; float ss = 0.f;
#pragma unroll
  for (int i = 0; i < 4; i++) {
    int c = tid + i * 256;
    float yv = g_y[dir][row][c];
    float z = __half2float(g_zxh[dir][row][c]);
    float gv = yv * (z / (1.f + expf(-z)));
    vals[i] = gv; ss += gv * gv;
  }
  __shared__ float red[256];
  red[tid] = ss; __syncthreads();
  for (int s = 128; s > 0; s >>= 1) { if (tid < s) red[tid] += red[tid + s]; __syncthreads(); }
  float sc = rsqrtf(red[0] * (1.f / DINNER) + 1e-5f);
#pragma unroll
  for (int i = 0; i < 4; i++) {
    int c = tid + i * 256;
    g_yh[dir][row][c] = __float2half(vals[i] * sc * gnorm_w[c]);
  }
}

// ---------------- launch ----------------
extern "C" void kernel_launch(void* const* d_in, const int* in_sizes, int n_in,
                              void* d_out, int out_size)
{
  (void)in_sizes; (void)n_in; (void)out_size;
  const float* x      = (const float*)d_in[0];
  const float* norm_w = (const float*)d_in[1];
  const float* op_w   = (const float*)d_in[2];
  const float* op_b   = (const float*)d_in[3];
  const float* in_w[2]    = {(const float*)d_in[4],  (const float*)d_in[12]};
  const float* conv_w[2]  = {(const float*)d_in[5],  (const float*)d_in[13]};
  const float* conv_b[2]  = {(const float*)d_in[6],  (const float*)d_in[14]};
  const float* dt_bias[2] = {(const float*)d_in[7],  (const float*)d_in[15]};
  const float* A_log[2]   = {(const float*)d_in[8],  (const float*)d_in[16]};
  const float* Dvec[2]    = {(const float*)d_in[9],  (const float*)d_in[17]};
  const float* gnorm[2]   = {(const float*)d_in[10], (const float*)d_in[18]};
  const float* outp_w[2]  = {(const float*)d_in[11], (const float*)d_in[19]};
  float* out = (float*)d_out;

  __half *pwi, *pwo, *pwp, *puh, *pyh, *podh, *pzxh;
  cudaGetSymbolAddress((void**)&pwi, wh_in);
  cudaGetSymbolAddress((void**)&pwo, wh_out);
  cudaGetSymbolAddress((void**)&pwp, wh_op);
  cudaGetSymbolAddress((void**)&puh, g_uh);
  cudaGetSymbolAddress((void**)&pyh, g_yh);
  cudaGetSymbolAddress((void**)&podh, g_odh);
  cudaGetSymbolAddress((void**)&pzxh, g_zxh);

  static int attr_set = 0;
  if (!attr_set) {
    cudaFuncSetAttribute(k_gemm_h, cudaFuncAttributeMaxDynamicSharedMemorySize, GSMEM);
    attr_set = 1;
  }

  // 1: weight convert + rmsnorm (fused)
  k_pre<<<dim3(BL, 6), 256>>>(
      x, norm_w,
      in_w[0],   pwi,                  DPROJ * DHALF,
      in_w[1],   pwi + DPROJ * DHALF,  DPROJ * DHALF,
      outp_w[0], pwo,                  DHALF * DINNER,
      outp_w[1], pwo + DHALF * DINNER, DHALF * DINNER,
      op_w,      pwp,                  DMODEL * DMODEL);

  // 2: in-proj, both dirs, fp16 output
  k_gemm_h<<<dim3((DPROJ + 127) / 128, BL / 128, 2), 128, GSMEM>>>(
      puh, pwi, nullptr, nullptr, nullptr, pzxh,
      DPROJ, DHALF, DPROJ, 0, 0, 0,
      (size_t)BL * DHALF, (size_t)DPROJ * DHALF, (size_t)BL * DPROJ);

  // 3: conv
  k_conv<<<2 * BL, 256>>>(conv_w[0], conv_b[0], dt_bias[0], A_log[0],
                          conv_w[1], conv_b[1], dt_bias[1], A_log[1]);

  // 4: scan — 256 blocks, static smem, simple loads
  k_scan<<<256, 128>>>(Dvec[0], Dvec[1]);

  // 5: gate
  k_gate<<<2 * BL, 256>>>(gnorm[0], gnorm[1]);

  // 6: out-proj, both dirs
  k_gemm_h<<<dim3(DHALF / 128, BL / 128, 2), 128, GSMEM>>>(
      pyh, pwo, nullptr, nullptr, nullptr, podh,
      DHALF, DINNER, DMODEL, 0, DHALF, 1,
      (size_t)BL * DINNER, (size_t)DHALF * DINNER, 0);

  // 7: final projection (+bias, +residual x)
  k_gemm_h<<<dim3(DMODEL / 128, BL / 128, 1), 128, GSMEM>>>(
      podh, pwp, op_b, x, out, nullptr,
      DMODEL, DMODEL, DMODEL, 0, 0, 0, 0, 0, 0);
}

// round 13
// speedup vs baseline: 1.2500x; 1.0145x over previous
#include <cuda_runtime.h>
#include <cuda_fp16.h>
#include <cstdint>
#include <cstddef>

#define BATCH   2
#define LSEQ    2048
#define BL      4096
#define DMODEL  1024
#define DHALF   512
#define DINNER  1024
#define DSTATE  128
#define NH      16
#define HD      64
#define CONVDIM 1280
#define DPROJ   2320

// ---------------- scratch ----------------
__device__ __half g_uh[2][BL][DHALF];
__device__ __half g_zxh[2][BL][DPROJ];
__device__ float  g_xc[2][BL][CONVDIM];
__device__ float  g_dt[2][BL][NH];
__device__ float  g_dA[2][BL][NH];
__device__ float  g_y[2][BL][DINNER];
__device__ __half g_yh[2][BL][DINNER];
__device__ __half g_odh[BL][DMODEL];
__device__ __half wh_in[2][DPROJ * DHALF];
__device__ __half wh_out[2][DHALF * DINNER];
__device__ __half wh_op[DMODEL * DMODEL];

// ---------------- helpers ----------------
__device__ __forceinline__ void cp16(uint32_t dst, const void* src, int szbytes) {
  asm volatile("cp.async.cg.shared.global [%0], [%1], 16, %2;"
               :: "r"(dst), "l"(src), "r"(szbytes) : "memory");
}
#define CP_COMMIT() asm volatile("cp.async.commit_group;" ::: "memory")
#define CP_WAIT1()  asm volatile("cp.async.wait_group 1;" ::: "memory")
#define CP_WAIT0()  asm volatile("cp.async.wait_group 0;" ::: "memory")

__device__ __forceinline__ void mma16816(float* c, const uint32_t* a, const uint32_t* b) {
  asm volatile(
    "mma.sync.aligned.m16n8k16.row.col.f32.f16.f16.f32 "
    "{%0,%1,%2,%3}, {%4,%5,%6,%7}, {%8,%9}, {%0,%1,%2,%3};"
    : "+f"(c[0]), "+f"(c[1]), "+f"(c[2]), "+f"(c[3])
    : "r"(a[0]), "r"(a[1]), "r"(a[2]), "r"(a[3]), "r"(b[0]), "r"(b[1]));
}
#define LDSM_X4(r0, r1, r2, r3, addr) \
  asm volatile("ldmatrix.sync.aligned.m8n8.x4.shared.b16 {%0,%1,%2,%3}, [%4];" \
               : "=r"(r0), "=r"(r1), "=r"(r2), "=r"(r3) : "r"(addr))

// ---------------- K1: fused weight-convert + RMSNorm/split/flip ----------------
__global__ __launch_bounds__(256) void k_pre(
    const float* __restrict__ x, const float* __restrict__ norm_w,
    const float* __restrict__ s0, __half* __restrict__ d0, int n0,
    const float* __restrict__ s1, __half* __restrict__ d1, int n1,
    const float* __restrict__ s2, __half* __restrict__ d2, int n2,
    const float* __restrict__ s3, __half* __restrict__ d3, int n3,
    const float* __restrict__ s4, __half* __restrict__ d4, int n4)
{
  int tid = threadIdx.x;
  if (blockIdx.y < 5) {
    const float* s; __half* d; int n;
    switch (blockIdx.y) {
      case 0: s = s0; d = d0; n = n0; break;
      case 1: s = s1; d = d1; n = n1; break;
      case 2: s = s2; d = d2; n = n2; break;
      case 3: s = s3; d = d3; n = n3; break;
      default: s = s4; d = d4; n = n4; break;
    }
    int i = (blockIdx.x * 256 + tid) * 4;
    if (i < n) {
      float4 v = *(const float4*)(s + i);
      *(__half2*)(d + i)     = __floats2half2_rn(v.x, v.y);
      *(__half2*)(d + i + 2) = __floats2half2_rn(v.z, v.w);
    }
    return;
  }
  int row = blockIdx.x;
  const float* xr = x + (size_t)row * DMODEL;
  float v[4]; float ss = 0.f;
#pragma unroll
  for (int i = 0; i < 4; i++) { v[i] = xr[tid + i * 256]; ss += v[i] * v[i]; }
  __shared__ float red[256];
  red[tid] = ss; __syncthreads();
  for (int s = 128; s > 0; s >>= 1) { if (tid < s) red[tid] += red[tid + s]; __syncthreads(); }
  float scale = rsqrtf(red[0] * (1.f / DMODEL) + 1e-5f);
  int l = row & 2047, rrow = (row & ~2047) + (2047 - l);
#pragma unroll
  for (int i = 0; i < 4; i++) {
    int c = tid + i * 256;
    float val = v[i] * scale * norm_w[c];
    if (c < DHALF) g_uh[0][row][c] = __float2half(val);
    else           g_uh[1][rrow][c - DHALF] = __float2half(val);
  }
}

// ---------------- K2: fp16 GEMM, 2-stage, warp 64x64, TKS=64, z merges dirs ----------------
#define TKS    64
#define SROW   72
#define TILEH  (128 * SROW)
#define STAGEB (2 * TILEH * 2)
#define GSMEM  (2 * STAGEB)

__global__ __launch_bounds__(128)
void k_gemm_h(const __half* __restrict__ A, const __half* __restrict__ W,
              const float* __restrict__ bias, const float* __restrict__ res,
              float* __restrict__ Cf, __half* __restrict__ Ch,
              int Nw, int K, int ldc, int col_off, int colOffZ, int flipZ,
              size_t aStrideZ, size_t wStrideZ, size_t cStrideZ)
{
  extern __shared__ __half sm[];
  int z = blockIdx.z;
  A += (size_t)z * aStrideZ;
  W += (size_t)z * wStrideZ;
  if (Cf) Cf += (size_t)z * cStrideZ; else Ch += (size_t)z * cStrideZ;
  int coff = col_off + z * colOffZ;
  int flip = flipZ ? z : 0;

  int tid = threadIdx.x;
  int wid = tid >> 5, lane = tid & 31;
  int g = lane >> 2, tg = lane & 3;
  int wm = wid & 1, wn = wid >> 1;
  int row0 = blockIdx.y * 128, col0 = blockIdx.x * 128;

  uint32_t sbase = (uint32_t)__cvta_generic_to_shared(sm);

  int arow = lane & 15, acol = (lane >> 4) * 8;
  int brow = ((lane >> 4) & 1) * 8 + (lane & 7);
  int bcol = ((lane >> 3) & 1) * 8;

  float acc[4][8][4];
#pragma unroll
  for (int mi = 0; mi < 4; mi++)
#pragma unroll
    for (int ni = 0; ni < 8; ni++)
#pragma unroll
      for (int r = 0; r < 4; r++) acc[mi][ni][r] = 0.f;

  int KT = K / TKS;

#define LOAD_STAGE(stg, k0)                                                       \
  {                                                                               \
    uint32_t ab = sbase + (stg) * STAGEB;                                         \
    uint32_t bb = ab + TILEH * 2;                                                 \
    _Pragma("unroll")                                                             \
    for (int i = 0; i < 8; i++) {                                                 \
      int idx = tid + i * 128;                                                    \
      int r = idx >> 3, q = idx & 7;                                              \
      cp16(ab + (uint32_t)((r * SROW + q * 8) * 2),                               \
           A + (size_t)(row0 + r) * K + (k0) + q * 8, 16);                        \
      int wr = col0 + r;                                                          \
      const __half* ws = W + (size_t)(wr < Nw ? wr : 0) * K + (k0) + q * 8;       \
      cp16(bb + (uint32_t)((r * SROW + q * 8) * 2), ws, (wr < Nw) ? 16 : 0);      \
    }                                                                             \
    CP_COMMIT();                                                                  \
  }

  LOAD_STAGE(0, 0)

  for (int kt = 0; kt < KT; kt++) {
    int buf = kt & 1;
    if (kt + 1 < KT) {
      LOAD_STAGE(buf ^ 1, (kt + 1) * TKS)
      CP_WAIT1();
    } else {
      CP_WAIT0();
    }
    __syncthreads();

    uint32_t ab = sbase + (uint32_t)buf * STAGEB;
    uint32_t bb = ab + TILEH * 2;
#pragma unroll
    for (int kk = 0; kk < TKS; kk += 16) {
      uint32_t af[4][4], bf[8][2];
#pragma unroll
      for (int mi = 0; mi < 4; mi++) {
        uint32_t addr = ab + (uint32_t)(((wm * 64 + mi * 16 + arow) * SROW + kk + acol) * 2);
        LDSM_X4(af[mi][0], af[mi][1], af[mi][2], af[mi][3], addr);
      }
#pragma unroll
      for (int nb = 0; nb < 4; nb++) {
        uint32_t addr = bb + (uint32_t)(((wn * 64 + nb * 16 + brow) * SROW + kk + bcol) * 2);
        LDSM_X4(bf[nb * 2][0], bf[nb * 2][1], bf[nb * 2 + 1][0], bf[nb * 2 + 1][1], addr);
      }
#pragma unroll
      for (int mi = 0; mi < 4; mi++)
#pragma unroll
        for (int ni = 0; ni < 8; ni++)
          mma16816(acc[mi][ni], af[mi], bf[ni]);
    }
    __syncthreads();
  }

#pragma unroll
  for (int mi = 0; mi < 4; mi++) {
#pragma unroll
    for (int hf = 0; hf < 2; hf++) {
      int m = row0 + wm * 64 + mi * 16 + g + hf * 8;
      int orow = flip ? ((m & ~2047) + (2047 - (m & 2047))) : m;
      const float* rrow = res ? (res + (size_t)m * ldc + coff) : nullptr;
#pragma unroll
      for (int ni = 0; ni < 8; ni++) {
        int n = col0 + wn * 64 + ni * 8 + 2 * tg;
        if (n < Nw) {
          float v0 = acc[mi][ni][hf * 2 + 0];
          float v1 = acc[mi][ni][hf * 2 + 1];
          if (bias) { v0 += bias[n]; v1 += bias[n + 1]; }
          if (rrow) { v0 += rrow[n]; v1 += rrow[n + 1]; }
          if (Cf) {
            float* crow = Cf + (size_t)orow * ldc + coff;
            crow[n] = v0; crow[n + 1] = v1;
          } else {
            __half* crow = Ch + (size_t)orow * ldc + coff;
            crow[n] = __float2half(v0); crow[n + 1] = __float2half(v1);
          }
        }
      }
    }
  }
}

// ---------------- K3: conv(4)+SiLU via smem staging, softplus(dt), dA ----------------
__global__ __launch_bounds__(256) void k_conv(
    const float* __restrict__ cw0, const float* __restrict__ cb0,
    const float* __restrict__ db0, const float* __restrict__ al0,
    const float* __restrict__ cw1, const float* __restrict__ cb1,
    const float* __restrict__ db1, const float* __restrict__ al1)
{
  int dir = blockIdx.x >> 12;
  int row = blockIdx.x & 4095;
  int tid = threadIdx.x;
  const float* conv_w  = dir ? cw1 : cw0;
  const float* conv_b  = dir ? cb1 : cb0;
  const float* dt_bias = dir ? db1 : db0;
  const float* A_log   = dir ? al1 : al0;
  int l = row & 2047, rb = row & ~2047;

  __shared__ __half sxb[4][CONVDIM];
  const int VPR = CONVDIM / 8;
  for (int i = tid; i < 4 * VPR; i += 256) {
    int kr = i / VPR, off = (i - kr * VPR) * 8;
    int ls = l - 3 + kr;
    if (ls >= 0)
      *(uint4*)&sxb[kr][off] = *(const uint4*)&g_zxh[dir][rb + ls][DINNER + off];
  }
  __syncthreads();

  for (int c = tid; c < CONVDIM; c += 256) {
    float acc = conv_b[c];
#pragma unroll
    for (int k = 0; k < 4; k++) {
      int ls = l - 3 + k;
      if (ls >= 0) acc = fmaf(conv_w[c * 4 + k], __half2float(sxb[k][c]), acc);
    }
    g_xc[dir][row][c] = acc / (1.f + expf(-acc));
  }
  if (tid < NH) {
    float d = __half2float(g_zxh[dir][row][DINNER + CONVDIM + tid]) + dt_bias[tid];
    float sp = (d > 20.f) ? d : log1pf(expf(d));
    g_dt[dir][row][tid] = sp;
    g_dA[dir][row][tid] = expf(-sp * expf(A_log[tid]));
  }
}

// ---------------- K4: scan — 256 blocks x 128 thr, 1p/thread, LDS.128 inner loop ----------------
#define TT 32
__global__ __launch_bounds__(128) void k_scan(const float* __restrict__ Df,
                                              const float* __restrict__ Db)
{
  int blk = blockIdx.x;               // 256 = dir(2) x b(2) x hh(16) x pq(4)
  int dir = blk >> 7;
  int rem = blk & 127;
  int b  = rem >> 6;
  int hh = (rem >> 2) & 15;
  int pq = rem & 3;
  int tid = threadIdx.x;
  int pl = tid >> 3, g = tid & 7;     // pl 0..15, g 0..7; thread owns p=pl, n=4g+32j4+e
  __shared__ float sB[TT][DSTATE];
  __shared__ float sC[TT][DSTATE];
  __shared__ float sx[TT][16];
  __shared__ float ss[TT][16];        // dt * x (precomputed by loader)
  __shared__ float sdA[TT];
  float h[16];
#pragma unroll
  for (int j = 0; j < 16; j++) h[j] = 0.f;
  float Dh = dir ? Db[hh] : Df[hh];
  int rowbase = b << 11;
  int xcol = hh * HD + pq * 16;
  int nb4 = g * 4;                    // base n for this thread's float4 groups

  for (int t0 = 0; t0 < LSEQ; t0 += TT) {
    __syncthreads();
    for (int i = tid; i < TT * DSTATE / 4; i += 128) {
      int tt = i >> 5, c4 = i & 31;
      int row = rowbase + t0 + tt;
      *(float4*)&sB[tt][c4 * 4] = *(const float4*)&g_xc[dir][row][DINNER + c4 * 4];
      *(float4*)&sC[tt][c4 * 4] = *(const float4*)&g_xc[dir][row][DINNER + DSTATE + c4 * 4];
    }
    for (int i = tid; i < TT * 4; i += 128) {
      int tt = i >> 2, q4 = (i & 3) * 4;
      int row = rowbase + t0 + tt;
      float4 xv = *(const float4*)&g_xc[dir][row][xcol + q4];
      float dtv = g_dt[dir][row][hh];
      *(float4*)&sx[tt][q4] = xv;
      ss[tt][q4 + 0] = dtv * xv.x;
      ss[tt][q4 + 1] = dtv * xv.y;
      ss[tt][q4 + 2] = dtv * xv.z;
      ss[tt][q4 + 3] = dtv * xv.w;
    }
    if (tid < TT) sdA[tid] = g_dA[dir][rowbase + t0 + tid][hh];
    __syncthreads();
#pragma unroll 4
    for (int tt = 0; tt < TT; tt++) {
      float dA = sdA[tt];
      float s  = ss[tt][pl];
      float a0 = 0.f, a1 = 0.f, a2 = 0.f, a3 = 0.f;
#pragma unroll
      for (int j4 = 0; j4 < 4; j4++) {
        float4 bv = *(const float4*)&sB[tt][nb4 + j4 * 32];
        float4 cv = *(const float4*)&sC[tt][nb4 + j4 * 32];
        int j = j4 * 4;
        h[j + 0] = fmaf(dA, h[j + 0], s * bv.x); a0 = fmaf(h[j + 0], cv.x, a0);
        h[j + 1] = fmaf(dA, h[j + 1], s * bv.y); a1 = fmaf(h[j + 1], cv.y, a1);
        h[j + 2] = fmaf(dA, h[j + 2], s * bv.z); a2 = fmaf(h[j + 2], cv.z, a2);
        h[j + 3] = fmaf(dA, h[j + 3], s * bv.w); a3 = fmaf(h[j + 3], cv.w, a3);
      }
      float acc = (a0 + a1) + (a2 + a3);
      acc += __shfl_xor_sync(0xffffffffu, acc, 1);
      acc += __shfl_xor_sync(0xffffffffu, acc, 2);
      acc += __shfl_xor_sync(0xffffffffu, acc, 4);
      if (g == 0)
        g_y[dir][rowbase + t0 + tt][xcol + pl] = acc + Dh * sx[tt][pl];
    }
  }
}

// ---------------- K5: gating + gated RMSNorm -> fp16, both dirs ----------------
__global__ __launch_bounds__(256) void k_gate(const float* __restrict__ gw0,
                                              const float* __restrict__ gw1)
{
  int dir = blockIdx.x >> 12;
  int row = blockIdx.x & 4095;
  int tid = threadIdx.x;
  const float* gnorm_w = dir ? gw1 : gw0;
  float vals[4]; float ss = 0.f;
#pragma unroll
  for (int i = 0; i < 4; i++) {
    int c = tid + i * 256;
    float yv = g_y[dir][row][c];
    float z = __half2float(g_zxh[dir][row][c]);
    float gv = yv * (z / (1.f + expf(-z)));
    vals[i] = gv; ss += gv * gv;
  }
  __shared__ float red[256];
  red[tid] = ss; __syncthreads();
  for (int s = 128; s > 0; s >>= 1) { if (tid < s) red[tid] += red[tid + s]; __syncthreads(); }
  float sc = rsqrtf(red[0] * (1.f / DINNER) + 1e-5f);
#pragma unroll
  for (int i = 0; i < 4; i++) {
    int c = tid + i * 256;
    g_yh[dir][row][c] = __float2half(vals[i] * sc * gnorm_w[c]);
  }
}

// ---------------- launch ----------------
extern "C" void kernel_launch(void* const* d_in, const int* in_sizes, int n_in,
                              void* d_out, int out_size)
{
  (void)in_sizes; (void)n_in; (void)out_size;
  const float* x      = (const float*)d_in[0];
  const float* norm_w = (const float*)d_in[1];
  const float* op_w   = (const float*)d_in[2];
  const float* op_b   = (const float*)d_in[3];
  const float* in_w[2]    = {(const float*)d_in[4],  (const float*)d_in[12]};
  const float* conv_w[2]  = {(const float*)d_in[5],  (const float*)d_in[13]};
  const float* conv_b[2]  = {(const float*)d_in[6],  (const float*)d_in[14]};
  const float* dt_bias[2] = {(const float*)d_in[7],  (const float*)d_in[15]};
  const float* A_log[2]   = {(const float*)d_in[8],  (const float*)d_in[16]};
  const float* Dvec[2]    = {(const float*)d_in[9],  (const float*)d_in[17]};
  const float* gnorm[2]   = {(const float*)d_in[10], (const float*)d_in[18]};
  const float* outp_w[2]  = {(const float*)d_in[11], (const float*)d_in[19]};
  float* out = (float*)d_out;

  __half *pwi, *pwo, *pwp, *puh, *pyh, *podh, *pzxh;
  cudaGetSymbolAddress((void**)&pwi, wh_in);
  cudaGetSymbolAddress((void**)&pwo, wh_out);
  cudaGetSymbolAddress((void**)&pwp, wh_op);
  cudaGetSymbolAddress((void**)&puh, g_uh);
  cudaGetSymbolAddress((void**)&pyh, g_yh);
  cudaGetSymbolAddress((void**)&podh, g_odh);
  cudaGetSymbolAddress((void**)&pzxh, g_zxh);

  static int attr_set = 0;
  if (!attr_set) {
    cudaFuncSetAttribute(k_gemm_h, cudaFuncAttributeMaxDynamicSharedMemorySize, GSMEM);
    attr_set = 1;
  }

  // 1: weight convert + rmsnorm (fused)
  k_pre<<<dim3(BL, 6), 256>>>(
      x, norm_w,
      in_w[0],   pwi,                  DPROJ * DHALF,
      in_w[1],   pwi + DPROJ * DHALF,  DPROJ * DHALF,
      outp_w[0], pwo,                  DHALF * DINNER,
      outp_w[1], pwo + DHALF * DINNER, DHALF * DINNER,
      op_w,      pwp,                  DMODEL * DMODEL);

  // 2: in-proj, both dirs, fp16 output
  k_gemm_h<<<dim3((DPROJ + 127) / 128, BL / 128, 2), 128, GSMEM>>>(
      puh, pwi, nullptr, nullptr, nullptr, pzxh,
      DPROJ, DHALF, DPROJ, 0, 0, 0,
      (size_t)BL * DHALF, (size_t)DPROJ * DHALF, (size_t)BL * DPROJ);

  // 3: conv
  k_conv<<<2 * BL, 256>>>(conv_w[0], conv_b[0], dt_bias[0], A_log[0],
                          conv_w[1], conv_b[1], dt_bias[1], A_log[1]);

  // 4: scan — 256 blocks, LDS.128 inner loop
  k_scan<<<256, 128>>>(Dvec[0], Dvec[1]);

  // 5: gate
  k_gate<<<2 * BL, 256>>>(gnorm[0], gnorm[1]);

  // 6: out-proj, both dirs
  k_gemm_h<<<dim3(DHALF / 128, BL / 128, 2), 128, GSMEM>>>(
      pyh, pwo, nullptr, nullptr, nullptr, podh,
      DHALF, DINNER, DMODEL, 0, DHALF, 1,
      (size_t)BL * DINNER, (size_t)DHALF * DINNER, 0);

  // 7: final projection (+bias, +residual x)
  k_gemm_h<<<dim3(DMODEL / 128, BL / 128, 1), 128, GSMEM>>>(
      podh, pwp, op_b, x, out, nullptr,
      DMODEL, DMODEL, DMODEL, 0, 0, 0, 0, 0, 0);
}